// round 7
// baseline (speedup 1.0000x reference)
#include <cuda_runtime.h>
#include <cuda_fp16.h>
#include <mma.h>
#include <math.h>
#include <stdint.h>

using namespace nvcuda;

#define BSZ    2
#define LSEQ   4096
#define NH     16
#define HD     128
#define NSTATE 256
#define CHUNK_ 256
#define NCH    16
#define NBB    4
#define DIN    2048
#define ZTOT   64

typedef __half hf;

// ---------------- static device scratch ----------------
__device__ float g_E2 [(size_t)NBB*NH*LSEQ];   // exp(cs_i - m(tile(i)))
__device__ float g_Wst[(size_t)NBB*NH*LSEQ];   // dt * exp(cs_last - cs)
__device__ float g_W0 [(size_t)NBB*NH*LSEQ];   // dt * exp(m0 - cs)
__device__ float g_W1 [(size_t)NBB*NH*LSEQ];   // dt * exp(m1 - cs)
__device__ float g_PS [ZTOT*NH*2];             // exp(m0), exp(m1)
__device__ float g_cd [ZTOT*NH];               // exp(cs_last)
__device__ __align__(16) hf g_BCf[(size_t)BSZ*LSEQ*2*NSTATE];   // BC fp16 [b][t][512]
__device__ __align__(16) hf g_XW [(size_t)NBB*DIN*LSEQ];        // wst*x^T [bb][d][t]
__device__ __align__(16) hf g_XB1[(size_t)NBB*DIN*LSEQ];        // w1*x^T  [bb][d][t]
__device__ __align__(16) hf g_XB0[(size_t)NBB*DIN*LSEQ/2];      // w0*x^T  [bb][d][c][128]
__device__ __align__(16) hf g_Btf[(size_t)ZTOT*NSTATE*CHUNK_];  // B^T fp16 [z][n][k]
__device__ __align__(16) hf g_CBf[(size_t)ZTOT*CHUNK_*CHUNK_];  // masked CB fp16 [z][i][k]
__device__ __align__(16) hf g_Sh [(size_t)ZTOT*NH*HD*NSTATE];   // states fp16 [z][h][p][n]
__device__ __align__(16) hf g_Pf [(size_t)ZTOT*NH*HD*NSTATE];   // prev fp16 (unscaled)
__device__ __align__(16) hf g_ybuf[(size_t)NBB*NH*LSEQ*HD];     // y fp16 [bb][h][t][p]

__device__ __forceinline__ size_t src_row(int bb, int t) {
    return (size_t)(bb & 1) * LSEQ + (size_t)(bb < 2 ? t : (LSEQ - 1 - t));
}
__device__ __forceinline__ uint32_t smem_u32(const void* p) {
    uint32_t a;
    asm("{ .reg .u64 t; cvta.to.shared.u64 t, %1; cvt.u32.u64 %0, t; }" : "=r"(a) : "l"(p));
    return a;
}
__device__ __forceinline__ void cpa16(uint32_t s, const void* g) {
    asm volatile("cp.async.ca.shared.global [%0], [%1], 16;" :: "r"(s), "l"(g));
}

// ---------------- generic 128x128 fp16 GEMM, 3-stage single-sync pipeline ----------------
// src(tile 0=A / 1=B, row 0..127, kb) -> pointer to 32 contiguous halfs.
// Output fp16 with optional per-row scale (escale), optional causal mask,
// optional scalar rescale of the accumulator before k-block midKb.
#define TILE_E  (128*40)
#define SMEM_GG 65536

template <bool MASK, typename SRC>
__device__ __forceinline__ void gemm128(int nkb, SRC src, hf* outp, int ldOut,
                                        const float* escale, int midKb, float midScale) {
    extern __shared__ __align__(16) hf sm[];
    const int tid = threadIdx.x;
    const int warp = tid >> 5, wr = warp >> 1, wc = warp & 1;
    const int r0 = tid & 127, t0 = tid >> 7;
    const uint32_t sbase = smem_u32(sm);

    wmma::fragment<wmma::accumulator, 16, 16, 16, float> acc[2][4];
#pragma unroll
    for (int i = 0; i < 2; i++)
#pragma unroll
        for (int j = 0; j < 4; j++) wmma::fill_fragment(acc[i][j], 0.0f);

    auto stage = [&](int kb) {
        if (kb < nkb) {
            int s = kb % 3;
            const hf* g = src(t0, r0, kb);
            uint32_t sa = sbase + (uint32_t)((s * 2 + t0) * TILE_E + r0 * 40) * 2;
            cpa16(sa, g); cpa16(sa + 16, g + 8); cpa16(sa + 32, g + 16); cpa16(sa + 48, g + 24);
        }
        asm volatile("cp.async.commit_group;" ::: "memory");
    };

    stage(0); stage(1);
    for (int kb = 0; kb < nkb; kb++) {
        asm volatile("cp.async.wait_group 1;" ::: "memory");
        __syncthreads();
        stage(kb + 2);
        if (kb == midKb) {
#pragma unroll
            for (int i = 0; i < 2; i++)
#pragma unroll
                for (int j = 0; j < 4; j++)
#pragma unroll
                    for (int e = 0; e < acc[i][j].num_elements; e++)
                        acc[i][j].x[e] *= midScale;
        }
        const hf* base = sm + (kb % 3) * 2 * TILE_E;
#pragma unroll
        for (int ks = 0; ks < 32; ks += 16) {
            wmma::fragment<wmma::matrix_a, 16, 16, 16, hf, wmma::row_major> af[2];
            wmma::load_matrix_sync(af[0], base + (wr * 32) * 40 + ks, 40);
            wmma::load_matrix_sync(af[1], base + (wr * 32 + 16) * 40 + ks, 40);
            wmma::fragment<wmma::matrix_b, 16, 16, 16, hf, wmma::col_major> bf[4];
#pragma unroll
            for (int j = 0; j < 4; j++)
                wmma::load_matrix_sync(bf[j], base + TILE_E + (wc * 64 + j * 16) * 40 + ks, 40);
#pragma unroll
            for (int i = 0; i < 2; i++)
#pragma unroll
                for (int j = 0; j < 4; j++)
                    wmma::mma_sync(acc[i][j], af[i], bf[j], acc[i][j]);
        }
    }
    __syncthreads();

    float* smf = (float*)sm;
#pragma unroll
    for (int i = 0; i < 2; i++)
#pragma unroll
        for (int j = 0; j < 4; j++)
            wmma::store_matrix_sync(smf + (size_t)(wr * 32 + i * 16) * 128 + wc * 64 + j * 16,
                                    acc[i][j], 128, wmma::mem_row_major);
    __syncthreads();
    float e = escale ? escale[r0] : 1.0f;
    hf* orow = outp + (size_t)r0 * ldOut + t0 * 64;
    const float* srow = smf + (size_t)r0 * 128 + t0 * 64;
#pragma unroll
    for (int j = 0; j < 64; j += 8) {
        hf tmp[8];
#pragma unroll
        for (int u = 0; u < 8; u++) {
            float v = srow[j + u] * e;
            if (MASK && (t0 * 64 + j + u > r0)) v = 0.f;
            tmp[u] = __float2half_rn(v);
        }
        *(uint4*)&orow[j] = *(uint4*)tmp;
    }
}

// ---------------- K1: softplus, cumsum, exp factors ----------------
__global__ void k_pre(const float* __restrict__ dt, const float* __restrict__ A_log) {
    int c = blockIdx.x, h = blockIdx.y, bb = blockIdx.z;
    int i = threadIdx.x;
    int t = c * CHUNK_ + i;
    int trow = (bb < 2) ? t : (LSEQ - 1 - t);
    int ch   = (bb < 2) ? h : (h + NH);
    float dtv = dt[((size_t)(bb & 1) * LSEQ + trow) * (2 * NH) + ch];
    float ds  = (dtv > 20.f) ? dtv : log1pf(expf(dtv));
    float dA  = ds * (-expf(A_log[h]));
    __shared__ float s[CHUNK_];
    s[i] = dA;
    __syncthreads();
    for (int off = 1; off < CHUNK_; off <<= 1) {
        float tv = (i >= off) ? s[i - off] : 0.f;
        __syncthreads();
        s[i] += tv;
        __syncthreads();
    }
    float cs = s[i], cl = s[CHUNK_ - 1];
    float m0 = s[64], m1 = s[192];
    size_t basei = ((size_t)bb * NH + h) * LSEQ + t;
    g_E2 [basei] = expf(cs - ((i < 128) ? m0 : m1));
    g_Wst[basei] = ds * expf(cl - cs);
    g_W0 [basei] = ds * expf(m0 - cs);
    g_W1 [basei] = ds * expf(m1 - cs);
    if (i == 0) {
        int zh = (bb * NCH + c) * NH + h;
        g_cd[zh] = expf(cl);
        g_PS[zh * 2]     = expf(m0);
        g_PS[zh * 2 + 1] = expf(m1);
    }
}

// ---------------- split BC -> fp16 [b][t][512] ----------------
__global__ void k_split_bc(const float* __restrict__ BC) {
    size_t row = blockIdx.x + (size_t)blockIdx.y * LSEQ;
    int col = threadIdx.x * 4;
    float4 v = *(const float4*)(BC + row * (2 * NSTATE) + col);
    hf tmp[4] = {__float2half_rn(v.x), __float2half_rn(v.y),
                 __float2half_rn(v.z), __float2half_rn(v.w)};
    *(uint2*)&g_BCf[row * (2 * NSTATE) + col] = *(uint2*)tmp;
}

// ---------------- transpose + scale x -> XW/XB1/XB0 fp16 [bb][d][t] ----------------
__global__ void k_xsplit(const float* __restrict__ x) {
    int bb = blockIdx.z;
    int tB = blockIdx.x * 32, dB = blockIdx.y * 32;
    __shared__ float s[32][33];
    int lr = threadIdx.x >> 5, lc = threadIdx.x & 31;
#pragma unroll
    for (int j = 0; j < 4; j++)
        s[lr + j * 8][lc] = x[src_row(bb, tB + lr + j * 8) * DIN + dB + lc];
    __syncthreads();
    int t = tB + lc;
    int c = t >> 8, tk = t & 255;
#pragma unroll
    for (int j = 0; j < 4; j++) {
        int d = dB + lr + j * 8;
        int h = d >> 7;
        float v = s[lc][lr + j * 8];
        size_t si = ((size_t)bb * NH + h) * LSEQ + t;
        size_t oi = ((size_t)bb * DIN + d) * LSEQ + t;
        g_XW [oi] = __float2half_rn(v * g_Wst[si]);
        g_XB1[oi] = __float2half_rn(v * g_W1[si]);
        if (tk < 128)
            g_XB0[(((size_t)bb * DIN + d) * NCH + c) * 128 + tk] = __float2half_rn(v * g_W0[si]);
    }
}

// ---------------- transpose B -> Bt fp16 [z][n][k] ----------------
__global__ void k_btsplit(const float* __restrict__ BC) {
    int z = blockIdx.z;
    int c = z % NCH, bb = z / NCH;
    int kB = blockIdx.x * 32, nB = blockIdx.y * 32;
    __shared__ float s[32][33];
    int lr = threadIdx.x >> 5, lc = threadIdx.x & 31;
#pragma unroll
    for (int j = 0; j < 4; j++)
        s[lr + j * 8][lc] = BC[src_row(bb, c * CHUNK_ + kB + lr + j * 8) * (2 * NSTATE) + nB + lc];
    __syncthreads();
#pragma unroll
    for (int j = 0; j < 4; j++)
        g_Btf[((size_t)z * NSTATE + nB + lr + j * 8) * CHUNK_ + kB + lc] =
            __float2half_rn(s[lc][lr + j * 8]);
}

// ---------------- CB GEMM: g_CBf[z][i][k] = mask * sum_n C[i,n] B[k,n] ----------------
__global__ void __launch_bounds__(256, 2) k_cb() {
    int iT = blockIdx.x, kT = blockIdx.y, z = blockIdx.z;
    if (iT == 0 && kT == 1) return;   // fully-masked tile, never read
    int c = z % NCH, bb = z / NCH;
    auto src = [&](int tile, int row, int kb) -> const hf* {
        if (tile == 0)
            return g_BCf + src_row(bb, c * CHUNK_ + iT * 128 + row) * (2 * NSTATE) + NSTATE + kb * 32;
        return g_BCf + src_row(bb, c * CHUNK_ + kT * 128 + row) * (2 * NSTATE) + kb * 32;
    };
    hf* out = g_CBf + ((size_t)z * CHUNK_ + iT * 128) * CHUNK_ + kT * 128;
    if (iT == kT) gemm128<true >(NSTATE / 32, src, out, CHUNK_, nullptr, -1, 1.f);
    else          gemm128<false>(NSTATE / 32, src, out, CHUNK_, nullptr, -1, 1.f);
}

// ---------------- states GEMM: g_Sh[z][h][p][n] = sum_k XW[p,k] Bt[n,k] ----------------
__global__ void __launch_bounds__(256, 2) k_states() {
    int nT = blockIdx.x, h = blockIdx.y, z = blockIdx.z;
    int c = z % NCH, bb = z / NCH;
    auto src = [&](int tile, int row, int kb) -> const hf* {
        if (tile == 0)
            return g_XW + ((size_t)bb * DIN + h * 128 + row) * LSEQ + c * CHUNK_ + kb * 32;
        return g_Btf + ((size_t)z * NSTATE + nT * 128 + row) * CHUNK_ + kb * 32;
    };
    gemm128<false>(CHUNK_ / 32, src,
                   g_Sh + (size_t)(z * NH + h) * HD * NSTATE + nT * 128, NSTATE,
                   nullptr, -1, 1.f);
}

// ---------------- inter-chunk scan: g_Sh -> unscaled prev fp16 ----------------
__global__ void k_scan() {
    int idx = blockIdx.x * blockDim.x + threadIdx.x;
    int n = idx & (NSTATE - 1);
    int p = (idx >> 8) & (HD - 1);
    int h = (idx >> 15) & (NH - 1);
    int bb = idx >> 19;
    size_t rest = ((size_t)h * HD + p) * NSTATE + n;
    const size_t stride = (size_t)NH * HD * NSTATE;
    float carry = 0.f;
    for (int c = 0; c < NCH; c++) {
        int zh = (bb * NCH + c) * NH + h;
        size_t off = (size_t)(bb * NCH + c) * stride + rest;
        float sv = __half2float(g_Sh[off]);
        g_Pf[off] = __float2half_rn(carry);
        carry = carry * g_cd[zh] + sv;
    }
}

// ---------------- y GEMM: ybuf = e2 * ( exp(m)*(C@prev) + CBm@XBm ) ----------------
__global__ void __launch_bounds__(256, 2) k_y() {
    int iT = blockIdx.x, h = blockIdx.y, z = blockIdx.z;
    int c = z % NCH, bb = z / NCH;
    const int p0kb = iT ? 8 : 4;     // intra-chunk K blocks
    auto src = [&](int tile, int row, int kb) -> const hf* {
        if (kb < 8) {                 // phase A: inter-chunk, n contraction
            int n0 = kb * 32;
            if (tile == 0)
                return g_BCf + src_row(bb, c * CHUNK_ + iT * 128 + row) * (2 * NSTATE) + NSTATE + n0;
            return g_Pf + ((size_t)(z * NH + h) * HD + row) * NSTATE + n0;
        }
        int pk = kb - 8;              // phase B: intra-chunk, k contraction
        if (tile == 0)
            return g_CBf + ((size_t)z * CHUNK_ + iT * 128 + row) * CHUNK_ + pk * 32;
        if (iT)
            return g_XB1 + ((size_t)bb * DIN + h * 128 + row) * LSEQ + c * CHUNK_ + pk * 32;
        return g_XB0 + (((size_t)bb * DIN + h * 128 + row) * NCH + c) * 128 + pk * 32;
    };
    int zh = (bb * NCH + c) * NH + h;
    float s = g_PS[zh * 2 + iT];      // exp(m_tile): rescales inter-chunk acc
    int t0 = c * CHUNK_ + iT * 128;
    gemm128<false>(8 + p0kb, src,
                   g_ybuf + ((size_t)(bb * NH + h) * LSEQ + t0) * HD, HD,
                   g_E2 + (size_t)(bb * NH + h) * LSEQ + t0, 8, s);
}

// ---------------- final combine ----------------
__global__ void k_final(const float* __restrict__ x, const float* __restrict__ W,
                        const float* __restrict__ Dp, float* __restrict__ out) {
    int t = blockIdx.x, b = blockIdx.y;
    __shared__ float xs[DIN];
    __shared__ float gate[NH];
    const float* xrow = x + ((size_t)b * LSEQ + t) * DIN;
    for (int d = threadIdx.x; d < DIN; d += 256) xs[d] = xrow[d];
    __syncthreads();
    int warp = threadIdx.x / 32, lane = threadIdx.x % 32;
#pragma unroll
    for (int hh = 0; hh < 2; hh++) {
        int h = warp * 2 + hh;
        const float* wrow = W + (size_t)h * DIN;
        float acc = 0.f;
        for (int d = lane; d < DIN; d += 32) acc += xs[d] * wrow[d];
#pragma unroll
        for (int o = 16; o; o >>= 1) acc += __shfl_down_sync(0xFFFFFFFFu, acc, o);
        if (lane == 0) gate[h] = acc + Dp[h];
    }
    __syncthreads();
    int tb = LSEQ - 1 - t;
    float* orow = out + ((size_t)b * LSEQ + t) * DIN;
    for (int d = threadIdx.x; d < DIN; d += 256) {
        int h = d >> 7, p = d & 127;
        float v = xs[d] * gate[h];
        if (t > 0)
            v += __half2float(g_ybuf[((size_t)(b * NH + h) * LSEQ + (t - 1)) * HD + p]);
        if (tb > 0)
            v += __half2float(g_ybuf[((size_t)((b + 2) * NH + h) * LSEQ + (tb - 1)) * HD + p]);
        orow[d] = v;
    }
}

// ---------------- launch ----------------
extern "C" void kernel_launch(void* const* d_in, const int* in_sizes, int n_in,
                              void* d_out, int out_size) {
    const float* x     = (const float*)d_in[0];
    const float* BC    = (const float*)d_in[1];
    const float* dt    = (const float*)d_in[2];
    const float* A_log = (const float*)d_in[3];
    const float* Dv    = (const float*)d_in[4];
    const float* W     = (const float*)d_in[5];
    float* out = (float*)d_out;

    cudaFuncSetAttribute(k_cb,     cudaFuncAttributeMaxDynamicSharedMemorySize, SMEM_GG);
    cudaFuncSetAttribute(k_states, cudaFuncAttributeMaxDynamicSharedMemorySize, SMEM_GG);
    cudaFuncSetAttribute(k_y,      cudaFuncAttributeMaxDynamicSharedMemorySize, SMEM_GG);

    k_pre     <<<dim3(NCH, NH, NBB), 256>>>(dt, A_log);
    k_split_bc<<<dim3(LSEQ, BSZ), 128>>>(BC);
    k_xsplit  <<<dim3(LSEQ / 32, DIN / 32, NBB), 256>>>(x);
    k_btsplit <<<dim3(8, 8, ZTOT), 256>>>(BC);
    k_cb      <<<dim3(2, 2, ZTOT), 256, SMEM_GG>>>();
    k_states  <<<dim3(2, NH, ZTOT), 256, SMEM_GG>>>();
    k_scan    <<<(NBB * NH * HD * NSTATE) / 256, 256>>>();
    k_y       <<<dim3(2, NH, ZTOT), 256, SMEM_GG>>>();
    k_final   <<<dim3(LSEQ, BSZ), 256>>>(x, W, Dv, out);
}